// round 7
// baseline (speedup 1.0000x reference)
#include <cuda_runtime.h>

#define BATCH 4096
#define TSEQ  20
#define INSZ  512
#define HSZ   512
#define RNK   20
#define G4    2048
#define NB    64          // batch rows per block
#define JT    64          // j columns per block
#define NJT   8           // number of j tiles
#define HSTRD 66          // ht row stride

// Scratch (no allocations allowed -> device globals)
__device__ float g_u[BATCH * TSEQ * RNK];        // [b][t][r] input projection
__device__ float g_c[BATCH * HSZ];               // cell state, tiled [(bc*8+jt)][bb][jjl]
__device__ float g_hu[2][NJT * BATCH * RNK];     // [parity][jt][b][r] h@whh_a partials

typedef unsigned long long ull;

__device__ __forceinline__ void ffma2(ull &d, ull a, ull b) {
    asm("fma.rn.f32x2 %0, %1, %2, %0;" : "+l"(d) : "l"(a), "l"(b));
}
__device__ __forceinline__ ull add2(ull a, ull b) {
    ull d; asm("add.rn.f32x2 %0, %1, %2;" : "=l"(d) : "l"(a), "l"(b)); return d;
}
__device__ __forceinline__ ull pack2(float x, float y) {
    ull r; asm("mov.b64 %0, {%1, %2};" : "=l"(r) : "f"(x), "f"(y)); return r;
}
__device__ __forceinline__ float2 unpack2(ull v) {
    float2 f; asm("mov.b64 {%0, %1}, %2;" : "=f"(f.x), "=f"(f.y) : "l"(v)); return f;
}
__device__ __forceinline__ float tanha(float x) {
    float y; asm("tanh.approx.f32 %0, %1;" : "=f"(y) : "f"(x)); return y;
}
__device__ __forceinline__ float siga(float x) {
    return fmaf(tanha(0.5f * x), 0.5f, 0.5f);
}

// ---------------------------------------------------------------------------
__global__ __launch_bounds__(256) void kPre(const float* __restrict__ x,
                                            const float* __restrict__ wa) {
    __shared__ __align__(16) float was[INSZ * RNK];
    for (int idx = threadIdx.x; idx < INSZ * RNK; idx += blockDim.x) was[idx] = wa[idx];
    __syncthreads();

    const int row = blockIdx.x * blockDim.x + threadIdx.x;
    const float4* xr = reinterpret_cast<const float4*>(x + (long)row * INSZ);

    ull acc[10];
#pragma unroll
    for (int q = 0; q < 10; q++) acc[q] = 0ull;

#pragma unroll 4
    for (int k4 = 0; k4 < INSZ / 4; k4++) {
        float4 xv = xr[k4];
#pragma unroll
        for (int i = 0; i < 4; i++) {
            float kv = (i == 0) ? xv.x : (i == 1) ? xv.y : (i == 2) ? xv.z : xv.w;
            ull ks = pack2(kv, kv);
            const ulonglong2* w2 = reinterpret_cast<const ulonglong2*>(was + (k4 * 4 + i) * RNK);
#pragma unroll
            for (int q = 0; q < 5; q++) {
                ulonglong2 wv = w2[q];
                ffma2(acc[2 * q + 0], ks, wv.x);
                ffma2(acc[2 * q + 1], ks, wv.y);
            }
        }
    }
    float* up = g_u + (long)row * RNK;
#pragma unroll
    for (int q = 0; q < 10; q++) {
        float2 f = unpack2(acc[q]);
        up[2 * q + 0] = f.x;
        up[2 * q + 1] = f.y;
    }
}

// ---------------------------------------------------------------------------
// smem partition (floats)
#define WT_OFF   0
#define WT_SZ    (40 * 256)                 // 10240  wT[k][gate*64+jjl]; reused for hu partials
#define VS_OFF   (WT_OFF + WT_SZ)
#define VS_SZ    (40 * NB * 2)              // 5120   vsplat[k][bb] as ull
#define BS_OFF   (VS_OFF + VS_SZ)
#define BS_SZ    256                        // bias [gate][jjl]
#define HT_OFF   (BS_OFF + BS_SZ)
#define HT_SZ    (NB * HSTRD)               // 4224
#define WA_OFF   (HT_OFF + HT_SZ)
#define WA_SZ    (JT * RNK)                 // 1280   wa[j][r]
#define SMEM_FLOATS (WA_OFF + WA_SZ)        // 21120 floats = 84480 B (2 blocks/SM)

__global__ __launch_bounds__(256, 2) void kStep(
    const float* __restrict__ wih_b, const float* __restrict__ b_ih,
    const float* __restrict__ whh_a, const float* __restrict__ whh_b,
    const float* __restrict__ b_hh,
    float* __restrict__ out, int t,
    float* __restrict__ hdst, float* __restrict__ cdst) {

    extern __shared__ __align__(16) float sm[];
    float* wT  = sm + WT_OFF;
    ull*   vsp = reinterpret_cast<ull*>(sm + VS_OFF);
    float* bs  = sm + BS_OFF;
    float* ht  = sm + HT_OFF;
    float* wa  = sm + WA_OFF;

    const int tid = threadIdx.x;
    const int jt = blockIdx.x, bc = blockIdx.y;
    const int j0 = jt * JT, b0 = bc * NB;
    const int mtile = tid & 31, ntile = tid >> 5;     // 32 x 8 thread grid
    const int jjl0 = mtile * 2, bb0 = ntile * 8;
    const long ctile = (long)(bc * NJT + jt) * (NB * JT);

    const float* rd = g_hu[t & 1];
    float*       wr = g_hu[(t + 1) & 1];

    // ---- prefetch this thread's c cells early (t==0 -> zeros) ----
    float2 creg[8];
    if (t > 0) {
#pragma unroll
        for (int n = 0; n < 8; n++)
            creg[n] = *reinterpret_cast<const float2*>(g_c + ctile + (bb0 + n) * JT + jjl0);
    } else {
#pragma unroll
        for (int n = 0; n < 8; n++) creg[n] = make_float2(0.f, 0.f);
    }

    // ---- stage wT[k][gate*64 + jjl] : pure float4 copy ----
#pragma unroll
    for (int it = 0; it < 10; it++) {
        int idx4 = it * 256 + tid;          // float4 index in [0, 2560)
        int r = idx4 >> 6;                  // 0..39
        int q = idx4 & 63;                  // float4 within 256-float row
        int gate = q >> 4, jjl4 = q & 15;
        const float* src = (r < RNK) ? (wih_b + r * G4) : (whh_b + (r - RNK) * G4);
        float4 v = reinterpret_cast<const float4*>(src + gate * 512 + j0)[jjl4];
        reinterpret_cast<float4*>(wT + r * 256 + gate * 64)[jjl4] = v;
    }
    // ---- bias [gate][jjl] ----
    {
        int gate = tid >> 6, jjl = tid & 63;
        int col = gate * 512 + j0 + jjl;
        bs[tid] = b_ih[col] + b_hh[col];
    }
    // ---- wa[j][r] = whh_a[(j0+j)][r] : straight float4 copy ----
    for (int idx = tid; idx < (JT * RNK) / 4; idx += 256)
        reinterpret_cast<float4*>(wa)[idx] =
            reinterpret_cast<const float4*>(whh_a + j0 * RNK)[idx];
    // ---- v = [u_t | sum of 8 hu partials], pre-splatted ----
    for (int idx = tid; idx < NB * 40; idx += 256) {
        int bb = idx / 40, r = idx % 40;
        int b = b0 + bb;
        float v;
        if (r < RNK) {
            v = g_u[b * (TSEQ * RNK) + t * RNK + r];
        } else if (t > 0) {
            int off = b * RNK + (r - RNK);
            float s0 = rd[off]                  + rd[BATCH * RNK + off];
            float s1 = rd[2 * BATCH * RNK + off] + rd[3 * BATCH * RNK + off];
            float s2 = rd[4 * BATCH * RNK + off] + rd[5 * BATCH * RNK + off];
            float s3 = rd[6 * BATCH * RNK + off] + rd[7 * BATCH * RNK + off];
            v = (s0 + s1) + (s2 + s3);
        } else {
            v = 0.f;
        }
        vsp[r * NB + bb] = pack2(v, v);
    }
    __syncthreads();

    // ---- main GEMM: acc[gate][n] = f32x2 over (jjl0, jjl0+1), bias folded ----
    ull acc[4][8];
#pragma unroll
    for (int g = 0; g < 4; g++) {
        ull bg = *reinterpret_cast<const ull*>(bs + g * 64 + jjl0);
#pragma unroll
        for (int n = 0; n < 8; n++) acc[g][n] = bg;
    }

#pragma unroll 8
    for (int k = 0; k < 40; k++) {
        ull wg[4];
#pragma unroll
        for (int g = 0; g < 4; g++)
            wg[g] = *reinterpret_cast<const ull*>(wT + k * 256 + g * 64 + jjl0);
        const ulonglong2* vrow = reinterpret_cast<const ulonglong2*>(vsp + k * NB + bb0);
        ulonglong2 v0 = vrow[0], v1 = vrow[1], v2 = vrow[2], v3 = vrow[3];
        ull vn[8] = {v0.x, v0.y, v1.x, v1.y, v2.x, v2.y, v3.x, v3.y};
#pragma unroll
        for (int g = 0; g < 4; g++)
#pragma unroll
            for (int n = 0; n < 8; n++)
                ffma2(acc[g][n], wg[g], vn[n]);
    }

    // ---- epilogue: full cell update in-thread (MUFU.TANH) ----
    const bool last = (hdst != nullptr);
#pragma unroll
    for (int n = 0; n < 8; n++) {
        int bb = bb0 + n;
        int b = b0 + bb;
        float2 i2 = unpack2(acc[0][n]);
        float2 f2 = unpack2(acc[1][n]);
        float2 g2 = unpack2(acc[2][n]);
        float2 o2 = unpack2(acc[3][n]);
        float2 cold = creg[n];
        float2 cc, hh;
        cc.x = fmaf(siga(f2.x), cold.x, siga(i2.x) * tanha(g2.x));
        cc.y = fmaf(siga(f2.y), cold.y, siga(i2.y) * tanha(g2.y));
        hh.x = siga(o2.x) * tanha(cc.x);
        hh.y = siga(o2.y) * tanha(cc.y);
        *reinterpret_cast<float2*>(g_c + ctile + bb * JT + jjl0) = cc;
        *reinterpret_cast<float2*>(out + ((long)b * TSEQ + t) * HSZ + j0 + jjl0) = hh;
        *reinterpret_cast<float2*>(ht + bb * HSTRD + jjl0) = hh;
        if (last) {
            *reinterpret_cast<float2*>(hdst + (long)b * HSZ + j0 + jjl0) = hh;
            *reinterpret_cast<float2*>(cdst + (long)b * HSZ + j0 + jjl0) = cc;
        }
    }
    __syncthreads();

    // ---- hu partials: thread (js, bb) accumulates ALL 20 r over 16 j ----
    // partial layout (reusing wT region): part[(rp*4+js)*64 + bb] as ull
    {
        ull* part = reinterpret_cast<ull*>(wT);
        const int js = tid >> 6, bb = tid & 63;    // 4 x 64
        ull a10[10];
#pragma unroll
        for (int rp = 0; rp < 10; rp++) a10[rp] = 0ull;
        const int jbeg = js * 16;
#pragma unroll
        for (int jj = 0; jj < 16; jj++) {
            int j = jbeg + jj;
            float hv = ht[bb * HSTRD + j];
            ull hs2 = pack2(hv, hv);
            const ulonglong2* war = reinterpret_cast<const ulonglong2*>(wa + j * RNK);
            ulonglong2 w0 = war[0], w1 = war[1], w2 = war[2], w3 = war[3], w4 = war[4];
            ffma2(a10[0], hs2, w0.x); ffma2(a10[1], hs2, w0.y);
            ffma2(a10[2], hs2, w1.x); ffma2(a10[3], hs2, w1.y);
            ffma2(a10[4], hs2, w2.x); ffma2(a10[5], hs2, w2.y);
            ffma2(a10[6], hs2, w3.x); ffma2(a10[7], hs2, w3.y);
            ffma2(a10[8], hs2, w4.x); ffma2(a10[9], hs2, w4.y);
        }
#pragma unroll
        for (int rp = 0; rp < 10; rp++)
            part[(rp * 4 + js) * 64 + bb] = a10[rp];
    }
    __syncthreads();

    // ---- reduce 4 jslices, write hu to global ----
    {
        const ull* part = reinterpret_cast<const ull*>(wT);
#pragma unroll
        for (int o = tid; o < NB * 10; o += 256) {
            int bb = o & 63, rp = o >> 6;
            ull s = add2(add2(part[(rp * 4 + 0) * 64 + bb], part[(rp * 4 + 1) * 64 + bb]),
                         add2(part[(rp * 4 + 2) * 64 + bb], part[(rp * 4 + 3) * 64 + bb]));
            float2 f = unpack2(s);
            *reinterpret_cast<float2*>(
                wr + jt * (BATCH * RNK) + (b0 + bb) * RNK + 2 * rp) = f;
        }
    }
}

// ---------------------------------------------------------------------------
extern "C" void kernel_launch(void* const* d_in, const int* in_sizes, int n_in,
                              void* d_out, int out_size) {
    const float* x     = (const float*)d_in[0];
    const float* wih_a = (const float*)d_in[1];
    const float* wih_b = (const float*)d_in[2];
    const float* b_ih  = (const float*)d_in[3];
    const float* whh_a = (const float*)d_in[4];
    const float* whh_b = (const float*)d_in[5];
    const float* b_hh  = (const float*)d_in[6];
    float* out = (float*)d_out;

    const long BTH = (long)BATCH * TSEQ * HSZ;
    float* hdst = nullptr;
    float* cdst = nullptr;
    if ((long)out_size >= BTH + 2L * BATCH * HSZ) {
        hdst = out + BTH;
        cdst = hdst + (long)BATCH * HSZ;
    }

    cudaFuncSetAttribute(kStep, cudaFuncAttributeMaxDynamicSharedMemorySize,
                         SMEM_FLOATS * 4);

    kPre<<<(BATCH * TSEQ) / 256, 256>>>(x, wih_a);
    for (int t = 0; t < TSEQ; t++) {
        bool lastT = (t == TSEQ - 1);
        kStep<<<dim3(NJT, 64), 256, SMEM_FLOATS * 4>>>(
            wih_b, b_ih, whh_a, whh_b, b_hh, out, t,
            lastT ? hdst : nullptr, lastT ? cdst : nullptr);
    }
}

// round 8
// speedup vs baseline: 1.0837x; 1.0837x over previous
#include <cuda_runtime.h>

#define BATCH 4096
#define TSEQ  20
#define INSZ  512
#define HSZ   512
#define RNK   20
#define G4    2048
#define NB    64          // batch rows per block
#define JT    128         // j columns per block
#define NJT   4
#define HSTRD 130         // ht row stride

// Scratch (no allocations allowed -> device globals)
__device__ float g_u[BATCH * TSEQ * RNK];        // [b][t][r] input projection
__device__ float g_c[BATCH * HSZ];               // cell state, tiled [(bc*4+jt)][bb][jjl]
__device__ float g_hu[2][NJT * BATCH * RNK];     // [parity][jt][b][r] h@whh_a partials

typedef unsigned long long ull;

__device__ __forceinline__ void ffma2(ull &d, ull a, ull b) {
    asm("fma.rn.f32x2 %0, %1, %2, %0;" : "+l"(d) : "l"(a), "l"(b));
}
__device__ __forceinline__ ull add2(ull a, ull b) {
    ull d; asm("add.rn.f32x2 %0, %1, %2;" : "=l"(d) : "l"(a), "l"(b)); return d;
}
__device__ __forceinline__ ull pack2(float x, float y) {
    ull r; asm("mov.b64 %0, {%1, %2};" : "=l"(r) : "f"(x), "f"(y)); return r;
}
__device__ __forceinline__ float2 unpack2(ull v) {
    float2 f; asm("mov.b64 {%0, %1}, %2;" : "=f"(f.x), "=f"(f.y) : "l"(v)); return f;
}
__device__ __forceinline__ float tanha(float x) {
    float y; asm("tanh.approx.f32 %0, %1;" : "=f"(y) : "f"(x)); return y;
}
__device__ __forceinline__ float siga(float x) {
    return fmaf(tanha(0.5f * x), 0.5f, 0.5f);
}

// ---------------------------------------------------------------------------
__global__ __launch_bounds__(256) void kPre(const float* __restrict__ x,
                                            const float* __restrict__ wa) {
    __shared__ __align__(16) float was[INSZ * RNK];
    for (int idx = threadIdx.x; idx < INSZ * RNK; idx += blockDim.x) was[idx] = wa[idx];
    __syncthreads();

    const int row = blockIdx.x * blockDim.x + threadIdx.x;
    const float4* xr = reinterpret_cast<const float4*>(x + (long)row * INSZ);

    ull acc[10];
#pragma unroll
    for (int q = 0; q < 10; q++) acc[q] = 0ull;

#pragma unroll 4
    for (int k4 = 0; k4 < INSZ / 4; k4++) {
        float4 xv = xr[k4];
#pragma unroll
        for (int i = 0; i < 4; i++) {
            float kv = (i == 0) ? xv.x : (i == 1) ? xv.y : (i == 2) ? xv.z : xv.w;
            ull ks = pack2(kv, kv);
            const ulonglong2* w2 = reinterpret_cast<const ulonglong2*>(was + (k4 * 4 + i) * RNK);
#pragma unroll
            for (int q = 0; q < 5; q++) {
                ulonglong2 wv = w2[q];
                ffma2(acc[2 * q + 0], ks, wv.x);
                ffma2(acc[2 * q + 1], ks, wv.y);
            }
        }
    }
    float* up = g_u + (long)row * RNK;
#pragma unroll
    for (int q = 0; q < 10; q++) {
        float2 f = unpack2(acc[q]);
        up[2 * q + 0] = f.x;
        up[2 * q + 1] = f.y;
    }
}

// ---------------------------------------------------------------------------
// smem partition (floats)
#define WT_OFF   0
#define WT_SZ    (40 * 512)                 // 20480  wT[k][gate*128+jjl]; reused for hu partials
#define VS_OFF   (WT_OFF + WT_SZ)
#define VS_SZ    (40 * NB * 2)              // 5120   vsplat[k][bb] as ull
#define BS_OFF   (VS_OFF + VS_SZ)
#define BS_SZ    512                        // bias [gate][jjl]
#define HT_OFF   (BS_OFF + BS_SZ)
#define HT_SZ    (NB * HSTRD)               // 8320
#define WA_OFF   (HT_OFF + HT_SZ)
#define WA_SZ    (JT * RNK)                 // 2560   wa[j][r]
#define SMEM_FLOATS (WA_OFF + WA_SZ)        // 36992 floats = 147968 B

__global__ __launch_bounds__(1024, 1) void kStep(
    const float* __restrict__ wih_b, const float* __restrict__ b_ih,
    const float* __restrict__ whh_a, const float* __restrict__ whh_b,
    const float* __restrict__ b_hh,
    float* __restrict__ out, int t,
    float* __restrict__ hdst, float* __restrict__ cdst) {

    extern __shared__ __align__(16) float sm[];
    float* wT  = sm + WT_OFF;
    ull*   vsp = reinterpret_cast<ull*>(sm + VS_OFF);
    float* bs  = sm + BS_OFF;
    float* ht  = sm + HT_OFF;
    float* wa  = sm + WA_OFF;

    const int tid = threadIdx.x;
    const int jt = blockIdx.x, bc = blockIdx.y;
    const int j0 = jt * JT, b0 = bc * NB;
    const int mtile = tid & 63, ntile = tid >> 6;     // 64 x 16 thread grid
    const int jjl0 = mtile * 2, bb0 = ntile * 4;
    const long ctile = (long)(bc * NJT + jt) * (NB * JT);

    const float* rd = g_hu[t & 1];
    float*       wr = g_hu[(t + 1) & 1];

    // ---- stage wT[k][gate*128 + jjl] : pure float4 copy ----
#pragma unroll
    for (int it = 0; it < 5; it++) {
        int idx4 = it * 1024 + tid;          // float4 index in [0, 5120)
        int r = idx4 >> 7;                   // 0..39
        int q = idx4 & 127;
        int gate = q >> 5, jjl4 = q & 31;
        const float* src = (r < RNK) ? (wih_b + r * G4) : (whh_b + (r - RNK) * G4);
        float4 v = reinterpret_cast<const float4*>(src + gate * 512 + j0)[jjl4];
        reinterpret_cast<float4*>(wT + r * 512 + gate * 128)[jjl4] = v;
    }
    // ---- bias [gate][jjl] ----
    if (tid < 512) {
        int gate = tid >> 7, jjl = tid & 127;
        int col = gate * 512 + j0 + jjl;
        bs[tid] = b_ih[col] + b_hh[col];
    }
    // ---- wa[j][r] = whh_a[(j0+j)][r] : straight float4 copy ----
    if (tid < (JT * RNK) / 4)
        reinterpret_cast<float4*>(wa)[tid] =
            reinterpret_cast<const float4*>(whh_a + j0 * RNK)[tid];
    // ---- v = [u_t | sum of 4 hu partials], pre-splatted ----
    for (int idx = tid; idx < NB * 40; idx += 1024) {
        int bb = idx / 40, r = idx % 40;
        int b = b0 + bb;
        float v;
        if (r < RNK) {
            v = g_u[b * (TSEQ * RNK) + t * RNK + r];
        } else if (t > 0) {
            int off = b * RNK + (r - RNK);
            v = (rd[off] + rd[BATCH * RNK + off])
              + (rd[2 * BATCH * RNK + off] + rd[3 * BATCH * RNK + off]);
        } else {
            v = 0.f;
        }
        vsp[r * NB + bb] = pack2(v, v);
    }
    __syncthreads();

    // ---- main GEMM: acc[gate][n] f32x2 over (jjl0, jjl0+1), bias folded ----
    ull acc[4][4];
#pragma unroll
    for (int g = 0; g < 4; g++) {
        ull bg = *reinterpret_cast<const ull*>(bs + g * 128 + jjl0);
#pragma unroll
        for (int n = 0; n < 4; n++) acc[g][n] = bg;
    }

#pragma unroll 8
    for (int k = 0; k < 40; k++) {
        ull wg[4];
#pragma unroll
        for (int g = 0; g < 4; g++)
            wg[g] = *reinterpret_cast<const ull*>(wT + k * 512 + g * 128 + jjl0);
        const ulonglong2* vrow = reinterpret_cast<const ulonglong2*>(vsp + k * NB + bb0);
        ulonglong2 v0 = vrow[0], v1 = vrow[1];
        ull vn[4] = {v0.x, v0.y, v1.x, v1.y};
#pragma unroll
        for (int g = 0; g < 4; g++)
#pragma unroll
            for (int n = 0; n < 4; n++)
                ffma2(acc[g][n], wg[g], vn[n]);
    }

    // ---- load c (post-GEMM to cut live range; latency hidden by 32 warps) ----
    float2 creg[4];
    if (t > 0) {
#pragma unroll
        for (int n = 0; n < 4; n++)
            creg[n] = *reinterpret_cast<const float2*>(g_c + ctile + (bb0 + n) * JT + jjl0);
    } else {
#pragma unroll
        for (int n = 0; n < 4; n++) creg[n] = make_float2(0.f, 0.f);
    }

    // ---- epilogue: full cell update in-thread (MUFU.TANH) ----
    const bool last = (hdst != nullptr);
#pragma unroll
    for (int n = 0; n < 4; n++) {
        int bb = bb0 + n;
        int b = b0 + bb;
        float2 i2 = unpack2(acc[0][n]);
        float2 f2 = unpack2(acc[1][n]);
        float2 g2 = unpack2(acc[2][n]);
        float2 o2 = unpack2(acc[3][n]);
        float2 cold = creg[n];
        float2 cc, hh;
        cc.x = fmaf(siga(f2.x), cold.x, siga(i2.x) * tanha(g2.x));
        cc.y = fmaf(siga(f2.y), cold.y, siga(i2.y) * tanha(g2.y));
        hh.x = siga(o2.x) * tanha(cc.x);
        hh.y = siga(o2.y) * tanha(cc.y);
        *reinterpret_cast<float2*>(g_c + ctile + bb * JT + jjl0) = cc;
        *reinterpret_cast<float2*>(out + ((long)b * TSEQ + t) * HSZ + j0 + jjl0) = hh;
        *reinterpret_cast<float2*>(ht + bb * HSTRD + jjl0) = hh;
        if (last) {
            *reinterpret_cast<float2*>(hdst + (long)b * HSZ + j0 + jjl0) = hh;
            *reinterpret_cast<float2*>(cdst + (long)b * HSZ + j0 + jjl0) = cc;
        }
    }
    __syncthreads();

    // ---- hu partials: thread (js, bb) accumulates ALL 20 r over 8 j ----
    // partial layout (reusing wT region): part[(rp*16+js)*64 + bb] as ull (80KB)
    {
        ull* part = reinterpret_cast<ull*>(wT);
        const int js = tid >> 6, bb = tid & 63;    // 16 x 64
        ull a10[10];
#pragma unroll
        for (int rp = 0; rp < 10; rp++) a10[rp] = 0ull;
        const int jbeg = js * 8;
#pragma unroll
        for (int jj = 0; jj < 8; jj++) {
            int j = jbeg + jj;
            float hv = ht[bb * HSTRD + j];
            ull hs2 = pack2(hv, hv);
            const ulonglong2* war = reinterpret_cast<const ulonglong2*>(wa + j * RNK);
            ulonglong2 w0 = war[0], w1 = war[1], w2 = war[2], w3 = war[3], w4 = war[4];
            ffma2(a10[0], hs2, w0.x); ffma2(a10[1], hs2, w0.y);
            ffma2(a10[2], hs2, w1.x); ffma2(a10[3], hs2, w1.y);
            ffma2(a10[4], hs2, w2.x); ffma2(a10[5], hs2, w2.y);
            ffma2(a10[6], hs2, w3.x); ffma2(a10[7], hs2, w3.y);
            ffma2(a10[8], hs2, w4.x); ffma2(a10[9], hs2, w4.y);
        }
#pragma unroll
        for (int rp = 0; rp < 10; rp++)
            part[(rp * 16 + js) * 64 + bb] = a10[rp];
    }
    __syncthreads();

    // ---- reduce 16 jslices, write hu to global ----
    if (tid < NB * 10) {
        const ull* part = reinterpret_cast<const ull*>(wT);
        int bb = tid & 63, rp = tid >> 6;
        ull s0 = add2(part[(rp * 16 + 0) * 64 + bb],  part[(rp * 16 + 1) * 64 + bb]);
        ull s1 = add2(part[(rp * 16 + 2) * 64 + bb],  part[(rp * 16 + 3) * 64 + bb]);
        ull s2 = add2(part[(rp * 16 + 4) * 64 + bb],  part[(rp * 16 + 5) * 64 + bb]);
        ull s3 = add2(part[(rp * 16 + 6) * 64 + bb],  part[(rp * 16 + 7) * 64 + bb]);
        ull s4 = add2(part[(rp * 16 + 8) * 64 + bb],  part[(rp * 16 + 9) * 64 + bb]);
        ull s5 = add2(part[(rp * 16 + 10) * 64 + bb], part[(rp * 16 + 11) * 64 + bb]);
        ull s6 = add2(part[(rp * 16 + 12) * 64 + bb], part[(rp * 16 + 13) * 64 + bb]);
        ull s7 = add2(part[(rp * 16 + 14) * 64 + bb], part[(rp * 16 + 15) * 64 + bb]);
        ull s = add2(add2(add2(s0, s1), add2(s2, s3)),
                     add2(add2(s4, s5), add2(s6, s7)));
        float2 f = unpack2(s);
        *reinterpret_cast<float2*>(
            wr + jt * (BATCH * RNK) + (b0 + bb) * RNK + 2 * rp) = f;
    }
}

// ---------------------------------------------------------------------------
extern "C" void kernel_launch(void* const* d_in, const int* in_sizes, int n_in,
                              void* d_out, int out_size) {
    const float* x     = (const float*)d_in[0];
    const float* wih_a = (const float*)d_in[1];
    const float* wih_b = (const float*)d_in[2];
    const float* b_ih  = (const float*)d_in[3];
    const float* whh_a = (const float*)d_in[4];
    const float* whh_b = (const float*)d_in[5];
    const float* b_hh  = (const float*)d_in[6];
    float* out = (float*)d_out;

    const long BTH = (long)BATCH * TSEQ * HSZ;
    float* hdst = nullptr;
    float* cdst = nullptr;
    if ((long)out_size >= BTH + 2L * BATCH * HSZ) {
        hdst = out + BTH;
        cdst = hdst + (long)BATCH * HSZ;
    }

    cudaFuncSetAttribute(kStep, cudaFuncAttributeMaxDynamicSharedMemorySize,
                         SMEM_FLOATS * 4);

    kPre<<<(BATCH * TSEQ) / 256, 256>>>(x, wih_a);
    for (int t = 0; t < TSEQ; t++) {
        bool lastT = (t == TSEQ - 1);
        kStep<<<dim3(NJT, 64), 1024, SMEM_FLOATS * 4>>>(
            wih_b, b_ih, whh_a, whh_b, b_hh, out, t,
            lastT ? hdst : nullptr, lastT ? cdst : nullptr);
    }
}

// round 9
// speedup vs baseline: 1.1872x; 1.0955x over previous
#include <cuda_runtime.h>

#define BATCH 4096
#define TSEQ  20
#define INSZ  512
#define HSZ   512
#define RNK   20
#define G4    2048
#define NB    64          // batch rows per sub-tile
#define JT    128         // j columns per block
#define NJT   4
#define NBLK  128         // persistent grid: 4 jt x 32 bc-pairs (all resident, 1/SM)
#define HSTRD 130

// Scratch (no allocations allowed -> device globals)
__device__ float g_u[BATCH * TSEQ * RNK];        // [b][t][r]
__device__ float g_hu[2][NJT * BATCH * RNK];     // [parity][jt][b][r]
__device__ unsigned g_bar;

typedef unsigned long long ull;

__device__ __forceinline__ void ffma2(ull &d, ull a, ull b) {
    asm("fma.rn.f32x2 %0, %1, %2, %0;" : "+l"(d) : "l"(a), "l"(b));
}
__device__ __forceinline__ ull add2(ull a, ull b) {
    ull d; asm("add.rn.f32x2 %0, %1, %2;" : "=l"(d) : "l"(a), "l"(b)); return d;
}
__device__ __forceinline__ ull pack2(float x, float y) {
    ull r; asm("mov.b64 %0, {%1, %2};" : "=l"(r) : "f"(x), "f"(y)); return r;
}
__device__ __forceinline__ float2 unpack2(ull v) {
    float2 f; asm("mov.b64 {%0, %1}, %2;" : "=f"(f.x), "=f"(f.y) : "l"(v)); return f;
}
__device__ __forceinline__ float tanha(float x) {
    float y; asm("tanh.approx.f32 %0, %1;" : "=f"(y) : "f"(x)); return y;
}
__device__ __forceinline__ float siga(float x) {
    return fmaf(tanha(0.5f * x), 0.5f, 0.5f);
}
__device__ __forceinline__ void bar_arrive(unsigned* p) {
    asm volatile("red.release.gpu.global.add.u32 [%0], 1;" :: "l"(p) : "memory");
}
__device__ __forceinline__ unsigned bar_peek(unsigned* p) {
    unsigned v;
    asm volatile("ld.acquire.gpu.global.u32 %0, [%1];" : "=r"(v) : "l"(p) : "memory");
    return v;
}

// ---------------------------------------------------------------------------
__global__ __launch_bounds__(256) void kPre(const float* __restrict__ x,
                                            const float* __restrict__ wa) {
    if (blockIdx.x == 0 && threadIdx.x == 0) g_bar = 0u;   // reset grid barrier

    __shared__ __align__(16) float was[INSZ * RNK];
    for (int idx = threadIdx.x; idx < INSZ * RNK; idx += blockDim.x) was[idx] = wa[idx];
    __syncthreads();

    const int row = blockIdx.x * blockDim.x + threadIdx.x;
    const float4* xr = reinterpret_cast<const float4*>(x + (long)row * INSZ);

    ull acc[10];
#pragma unroll
    for (int q = 0; q < 10; q++) acc[q] = 0ull;

#pragma unroll 4
    for (int k4 = 0; k4 < INSZ / 4; k4++) {
        float4 xv = xr[k4];
#pragma unroll
        for (int i = 0; i < 4; i++) {
            float kv = (i == 0) ? xv.x : (i == 1) ? xv.y : (i == 2) ? xv.z : xv.w;
            ull ks = pack2(kv, kv);
            const ulonglong2* w2 = reinterpret_cast<const ulonglong2*>(was + (k4 * 4 + i) * RNK);
#pragma unroll
            for (int q = 0; q < 5; q++) {
                ulonglong2 wv = w2[q];
                ffma2(acc[2 * q + 0], ks, wv.x);
                ffma2(acc[2 * q + 1], ks, wv.y);
            }
        }
    }
    float* up = g_u + (long)row * RNK;
#pragma unroll
    for (int q = 0; q < 10; q++) {
        float2 f = unpack2(acc[q]);
        up[2 * q + 0] = f.x;
        up[2 * q + 1] = f.y;
    }
}

// ---------------------------------------------------------------------------
// smem partition (floats)
#define WT_OFF   0
#define WT_SZ    (40 * 512)                 // 20480  wT[k][gate*128+jjl]   (persistent)
#define VS_OFF   (WT_OFF + WT_SZ)
#define VS_SZ    (40 * NB * 2)              // 5120   vsplat[k][bb] ull; reused for hu partials
#define BS_OFF   (VS_OFF + VS_SZ)
#define BS_SZ    512                        // bias   (persistent)
#define HT_OFF   (BS_OFF + BS_SZ)
#define HT_SZ    (NB * HSTRD)               // 8320
#define WA_OFF   (HT_OFF + HT_SZ)
#define WA_SZ    (JT * RNK)                 // 2560   wa[j][r]             (persistent)
#define CS_OFF   (WA_OFF + WA_SZ)
#define CS_SZ    (2 * NB * JT)              // 16384  c state, both subs   (persistent)
#define SMEM_FLOATS (CS_OFF + CS_SZ)        // 53376 floats = 213504 B -> 1 block/SM

__global__ __launch_bounds__(512, 1) void kStep(
    const float* __restrict__ wih_b, const float* __restrict__ b_ih,
    const float* __restrict__ whh_a, const float* __restrict__ whh_b,
    const float* __restrict__ b_hh,
    float* __restrict__ out,
    float* __restrict__ hdst, float* __restrict__ cdst) {

    extern __shared__ __align__(16) float sm[];
    float* wT  = sm + WT_OFF;
    ull*   vsp = reinterpret_cast<ull*>(sm + VS_OFF);
    float* bs  = sm + BS_OFF;
    float* ht  = sm + HT_OFF;
    float* wa  = sm + WA_OFF;
    float* cs  = sm + CS_OFF;

    const int tid = threadIdx.x;
    const int jt = blockIdx.x & 3, bc2 = blockIdx.x >> 2;   // 4 x 32
    const int j0 = jt * JT;
    const int mtile = tid & 63, ntile = tid >> 6;           // 64 x 8
    const int jjl0 = mtile * 2, bb0 = ntile * 8;

    // ======== one-time staging (weights, bias, wa) ========
#pragma unroll
    for (int it = 0; it < 10; it++) {
        int idx4 = it * 512 + tid;
        int r = idx4 >> 7;
        int q = idx4 & 127;
        int gate = q >> 5, jjl4 = q & 31;
        const float* src = (r < RNK) ? (wih_b + r * G4) : (whh_b + (r - RNK) * G4);
        float4 v = reinterpret_cast<const float4*>(src + gate * 512 + j0)[jjl4];
        reinterpret_cast<float4*>(wT + r * 512 + gate * 128)[jjl4] = v;
    }
    {
        int gate = tid >> 7, jjl = tid & 127;
        int col = gate * 512 + j0 + jjl;
        bs[tid] = b_ih[col] + b_hh[col];
    }
    for (int idx = tid; idx < (JT * RNK) / 4; idx += 512)
        reinterpret_cast<float4*>(wa)[idx] =
            reinterpret_cast<const float4*>(whh_a + j0 * RNK)[idx];
    __syncthreads();

    // ======== time loop ========
    for (int t = 0; t < TSEQ; t++) {
        const float* rd = g_hu[t & 1];
        float*       wr = g_hu[(t + 1) & 1];

#pragma unroll 1
        for (int sub = 0; sub < 2; sub++) {
            const int b0 = (bc2 * 2 + sub) * NB;
            float* csub = cs + sub * (NB * JT);

            // ---- stage v = [u_t | sum of 4 hu partials] (L2 reads, no L1) ----
            for (int idx = tid; idx < NB * 40; idx += 512) {
                int bb = idx / 40, r = idx % 40;
                int b = b0 + bb;
                float v;
                if (r < RNK) {
                    v = g_u[b * (TSEQ * RNK) + t * RNK + r];
                } else if (t > 0) {
                    int off = b * RNK + (r - RNK);
                    v = (__ldcg(rd + off) + __ldcg(rd + BATCH * RNK + off))
                      + (__ldcg(rd + 2 * BATCH * RNK + off) + __ldcg(rd + 3 * BATCH * RNK + off));
                } else {
                    v = 0.f;
                }
                vsp[r * NB + bb] = pack2(v, v);
            }
            __syncthreads();

            // ---- GEMM: acc[gate][n] f32x2 over (jjl0, jjl0+1), bias folded ----
            ull acc[4][8];
#pragma unroll
            for (int g = 0; g < 4; g++) {
                ull bg = *reinterpret_cast<const ull*>(bs + g * 128 + jjl0);
#pragma unroll
                for (int n = 0; n < 8; n++) acc[g][n] = bg;
            }
#pragma unroll 8
            for (int k = 0; k < 40; k++) {
                ull wg[4];
#pragma unroll
                for (int g = 0; g < 4; g++)
                    wg[g] = *reinterpret_cast<const ull*>(wT + k * 512 + g * 128 + jjl0);
                const ulonglong2* vrow = reinterpret_cast<const ulonglong2*>(vsp + k * NB + bb0);
                ulonglong2 v0 = vrow[0], v1 = vrow[1], v2 = vrow[2], v3 = vrow[3];
                ull vn[8] = {v0.x, v0.y, v1.x, v1.y, v2.x, v2.y, v3.x, v3.y};
#pragma unroll
                for (int g = 0; g < 4; g++)
#pragma unroll
                    for (int n = 0; n < 8; n++)
                        ffma2(acc[g][n], wg[g], vn[n]);
            }

            // ---- epilogue: cell update; c kept in smem ----
            const bool lastT = (t == TSEQ - 1);
#pragma unroll
            for (int n = 0; n < 8; n++) {
                int bb = bb0 + n;
                int b = b0 + bb;
                float2 i2 = unpack2(acc[0][n]);
                float2 f2 = unpack2(acc[1][n]);
                float2 g2 = unpack2(acc[2][n]);
                float2 o2 = unpack2(acc[3][n]);
                float2 cold = (t > 0)
                    ? *reinterpret_cast<const float2*>(csub + bb * JT + jjl0)
                    : make_float2(0.f, 0.f);
                float2 cc, hh;
                cc.x = fmaf(siga(f2.x), cold.x, siga(i2.x) * tanha(g2.x));
                cc.y = fmaf(siga(f2.y), cold.y, siga(i2.y) * tanha(g2.y));
                hh.x = siga(o2.x) * tanha(cc.x);
                hh.y = siga(o2.y) * tanha(cc.y);
                *reinterpret_cast<float2*>(csub + bb * JT + jjl0) = cc;
                *reinterpret_cast<float2*>(out + ((long)b * TSEQ + t) * HSZ + j0 + jjl0) = hh;
                *reinterpret_cast<float2*>(ht + bb * HSTRD + jjl0) = hh;
                if (lastT && hdst) {
                    *reinterpret_cast<float2*>(hdst + (long)b * HSZ + j0 + jjl0) = hh;
                    *reinterpret_cast<float2*>(cdst + (long)b * HSZ + j0 + jjl0) = cc;
                }
            }
            __syncthreads();

            // ---- hu partials into vsp region: 4 jslices x 64 bb (256 threads) ----
            {
                ull* part = vsp;                    // vsp dead after GEMM
                if (tid < 256) {
                    const int js = tid >> 6, bb = tid & 63;   // 4 x 64
                    ull a10[10];
#pragma unroll
                    for (int rp = 0; rp < 10; rp++) a10[rp] = 0ull;
                    const int jbeg = js * 32;
#pragma unroll 4
                    for (int jj = 0; jj < 32; jj++) {
                        int j = jbeg + jj;
                        float hv = ht[bb * HSTRD + j];
                        ull hs2 = pack2(hv, hv);
                        const ulonglong2* war = reinterpret_cast<const ulonglong2*>(wa + j * RNK);
                        ulonglong2 w0 = war[0], w1 = war[1], w2 = war[2], w3 = war[3], w4 = war[4];
                        ffma2(a10[0], hs2, w0.x); ffma2(a10[1], hs2, w0.y);
                        ffma2(a10[2], hs2, w1.x); ffma2(a10[3], hs2, w1.y);
                        ffma2(a10[4], hs2, w2.x); ffma2(a10[5], hs2, w2.y);
                        ffma2(a10[6], hs2, w3.x); ffma2(a10[7], hs2, w3.y);
                        ffma2(a10[8], hs2, w4.x); ffma2(a10[9], hs2, w4.y);
                    }
#pragma unroll
                    for (int rp = 0; rp < 10; rp++)
                        part[(rp * 4 + js) * 64 + bb] = a10[rp];
                }
            }
            __syncthreads();

            // ---- reduce 4 jslices -> g_hu ----
            {
                const ull* part = vsp;
                for (int o = tid; o < NB * 10; o += 512) {
                    int bb = o & 63, rp = o >> 6;
                    ull s = add2(add2(part[(rp * 4 + 0) * 64 + bb], part[(rp * 4 + 1) * 64 + bb]),
                                 add2(part[(rp * 4 + 2) * 64 + bb], part[(rp * 4 + 3) * 64 + bb]));
                    float2 f = unpack2(s);
                    *reinterpret_cast<float2*>(
                        wr + jt * (BATCH * RNK) + (b0 + bb) * RNK + 2 * rp) = f;
                }
            }
            __syncthreads();   // protect vsp before next sub/step staging
        }

        // ---- grid barrier between steps ----
        if (t < TSEQ - 1) {
            if (tid == 0) {
                bar_arrive(&g_bar);
                unsigned target = (unsigned)NBLK * (unsigned)(t + 1);
                while (bar_peek(&g_bar) < target) __nanosleep(64);
            }
            __syncthreads();
        }
    }
}

// ---------------------------------------------------------------------------
extern "C" void kernel_launch(void* const* d_in, const int* in_sizes, int n_in,
                              void* d_out, int out_size) {
    const float* x     = (const float*)d_in[0];
    const float* wih_a = (const float*)d_in[1];
    const float* wih_b = (const float*)d_in[2];
    const float* b_ih  = (const float*)d_in[3];
    const float* whh_a = (const float*)d_in[4];
    const float* whh_b = (const float*)d_in[5];
    const float* b_hh  = (const float*)d_in[6];
    float* out = (float*)d_out;

    const long BTH = (long)BATCH * TSEQ * HSZ;
    float* hdst = nullptr;
    float* cdst = nullptr;
    if ((long)out_size >= BTH + 2L * BATCH * HSZ) {
        hdst = out + BTH;
        cdst = hdst + (long)BATCH * HSZ;
    }

    cudaFuncSetAttribute(kStep, cudaFuncAttributeMaxDynamicSharedMemorySize,
                         SMEM_FLOATS * 4);

    kPre<<<(BATCH * TSEQ) / 256, 256>>>(x, wih_a);
    kStep<<<NBLK, 512, SMEM_FLOATS * 4>>>(wih_b, b_ih, whh_a, whh_b, b_hh,
                                          out, hdst, cdst);
}

// round 11
// speedup vs baseline: 1.2733x; 1.0726x over previous
#include <cuda_runtime.h>

#define BATCH 4096
#define TSEQ  20
#define INSZ  512
#define HSZ   512
#define RNK   20
#define G4    2048
#define NB    56          // batch rows per sub-tile
#define JT    128         // j columns per block
#define NJT   4
#define NBC   37
#define NBLK  (NJT * NBC) // 148 persistent blocks, all resident
#define HSTRD 130

// Scratch (no allocations allowed -> device globals)
__device__ float g_u[TSEQ * RNK * BATCH];        // [t][r][b]  (transposed)
__device__ float g_hu[2][RNK * NJT * BATCH];     // [parity][r][jt][b]
__device__ unsigned g_bar;

typedef unsigned long long ull;

__device__ __forceinline__ void ffma2(ull &d, ull a, ull b) {
    asm("fma.rn.f32x2 %0, %1, %2, %0;" : "+l"(d) : "l"(a), "l"(b));
}
__device__ __forceinline__ ull add2(ull a, ull b) {
    ull d; asm("add.rn.f32x2 %0, %1, %2;" : "=l"(d) : "l"(a), "l"(b)); return d;
}
__device__ __forceinline__ ull pack2(float x, float y) {
    ull r; asm("mov.b64 %0, {%1, %2};" : "=l"(r) : "f"(x), "f"(y)); return r;
}
__device__ __forceinline__ float2 unpack2(ull v) {
    float2 f; asm("mov.b64 {%0, %1}, %2;" : "=f"(f.x), "=f"(f.y) : "l"(v)); return f;
}
__device__ __forceinline__ float tanha(float x) {
    float y; asm("tanh.approx.f32 %0, %1;" : "=f"(y) : "f"(x)); return y;
}
__device__ __forceinline__ float siga(float x) {
    return fmaf(tanha(0.5f * x), 0.5f, 0.5f);
}
__device__ __forceinline__ void bar_arrive(unsigned* p) {
    asm volatile("red.release.gpu.global.add.u32 [%0], 1;" :: "l"(p) : "memory");
}
__device__ __forceinline__ unsigned bar_peek(unsigned* p) {
    unsigned v;
    asm volatile("ld.acquire.gpu.global.u32 %0, [%1];" : "=r"(v) : "l"(p) : "memory");
    return v;
}

// ---------------------------------------------------------------------------
// u[t][r][b]; thread row' = t*BATCH + b  (coalesced stores per r)
__global__ __launch_bounds__(256) void kPre(const float* __restrict__ x,
                                            const float* __restrict__ wa) {
    if (blockIdx.x == 0 && threadIdx.x == 0) g_bar = 0u;

    __shared__ __align__(16) float was[INSZ * RNK];
    for (int idx = threadIdx.x; idx < INSZ * RNK; idx += blockDim.x) was[idx] = wa[idx];
    __syncthreads();

    const int rowp = blockIdx.x * blockDim.x + threadIdx.x;   // t*BATCH + b
    const int t = rowp >> 12, b = rowp & (BATCH - 1);
    const float4* xr = reinterpret_cast<const float4*>(x + ((long)b * TSEQ + t) * INSZ);

    ull acc[10];
#pragma unroll
    for (int q = 0; q < 10; q++) acc[q] = 0ull;

#pragma unroll 4
    for (int k4 = 0; k4 < INSZ / 4; k4++) {
        float4 xv = xr[k4];
#pragma unroll
        for (int i = 0; i < 4; i++) {
            float kv = (i == 0) ? xv.x : (i == 1) ? xv.y : (i == 2) ? xv.z : xv.w;
            ull ks = pack2(kv, kv);
            const ulonglong2* w2 = reinterpret_cast<const ulonglong2*>(was + (k4 * 4 + i) * RNK);
#pragma unroll
            for (int q = 0; q < 5; q++) {
                ulonglong2 wv = w2[q];
                ffma2(acc[2 * q + 0], ks, wv.x);
                ffma2(acc[2 * q + 1], ks, wv.y);
            }
        }
    }
#pragma unroll
    for (int q = 0; q < 10; q++) {
        float2 f = unpack2(acc[q]);
        g_u[(t * RNK + 2 * q + 0) * BATCH + b] = f.x;
        g_u[(t * RNK + 2 * q + 1) * BATCH + b] = f.y;
    }
}

// ---------------------------------------------------------------------------
// smem partition (floats)
#define WT_OFF   0
#define WT_SZ    (40 * 512)                 // wT[k][gate*128+jjl]  (persistent)
#define VS_OFF   (WT_OFF + WT_SZ)
#define VS_SZ    (40 * NB * 2)              // 4480: vsplat[k][bb] ull; reused for hu partials
#define BS_OFF   (VS_OFF + VS_SZ)
#define BS_SZ    512                        // bias (persistent)
#define HT_OFF   (BS_OFF + BS_SZ)
#define HT_SZ    (NB * HSTRD)               // 7280
#define WA_OFF   (HT_OFF + HT_SZ)
#define WA_SZ    (JT * RNK)                 // 2560: wa[j][r]  (persistent)
#define CS_OFF   (WA_OFF + WA_SZ)
#define CS_SZ    (2 * NB * JT)              // 14336: c state, both subs (persistent)
#define SMEM_FLOATS (CS_OFF + CS_SZ)        // 49648 floats = 198592 B -> 1 block/SM

template<int K0, int K1>
__device__ __forceinline__ void gemm_part(ull (&acc)[4][7], const float* wT,
                                          const ull* vsp, int jjl0, int bb0) {
#pragma unroll 4
    for (int k = K0; k < K1; k++) {
        ull wg[4];
#pragma unroll
        for (int g = 0; g < 4; g++)
            wg[g] = *reinterpret_cast<const ull*>(wT + k * 512 + g * 128 + jjl0);
        ull vn[7];
#pragma unroll
        for (int n = 0; n < 7; n++) vn[n] = vsp[k * NB + bb0 + n];
#pragma unroll
        for (int g = 0; g < 4; g++)
#pragma unroll
            for (int n = 0; n < 7; n++)
                ffma2(acc[g][n], wg[g], vn[n]);
    }
}

__global__ __launch_bounds__(512, 1) void kStep(
    const float* __restrict__ wih_b, const float* __restrict__ b_ih,
    const float* __restrict__ whh_a, const float* __restrict__ whh_b,
    const float* __restrict__ b_hh,
    float* __restrict__ out,
    float* __restrict__ hdst, float* __restrict__ cdst) {

    extern __shared__ __align__(16) float sm[];
    float* wT  = sm + WT_OFF;
    ull*   vsp = reinterpret_cast<ull*>(sm + VS_OFF);
    float* bs  = sm + BS_OFF;
    float* ht  = sm + HT_OFF;
    float* wa  = sm + WA_OFF;
    float* cs  = sm + CS_OFF;

    const int tid = threadIdx.x;
    const int jt = blockIdx.x & 3, bc = blockIdx.x >> 2;   // 4 x 37
    const int j0 = jt * JT;
    const int mtile = tid & 63, ntile = tid >> 6;          // 64 x 8
    const int jjl0 = mtile * 2, bb0 = ntile * 7;           // 7 rows/thread

    // ======== one-time staging ========
#pragma unroll
    for (int it = 0; it < 10; it++) {
        int idx4 = it * 512 + tid;
        int r = idx4 >> 7;
        int q = idx4 & 127;
        int gate = q >> 5, jjl4 = q & 31;
        const float* src = (r < RNK) ? (wih_b + r * G4) : (whh_b + (r - RNK) * G4);
        float4 v = reinterpret_cast<const float4*>(src + gate * 512 + j0)[jjl4];
        reinterpret_cast<float4*>(wT + r * 512 + gate * 128)[jjl4] = v;
    }
    {
        int gate = tid >> 7, jjl = tid & 127;
        int col = gate * 512 + j0 + jjl;
        bs[tid] = b_ih[col] + b_hh[col];
    }
    for (int idx = tid; idx < (JT * RNK) / 4; idx += 512)
        reinterpret_cast<float4*>(wa)[idx] =
            reinterpret_cast<const float4*>(whh_a + j0 * RNK)[idx];
    __syncthreads();

    // ======== time loop ========
    for (int t = 0; t < TSEQ; t++) {
        const float* rd = g_hu[t & 1];
        float*       wr = g_hu[(t + 1) & 1];
        const bool lastT = (t == TSEQ - 1);

#pragma unroll 1
        for (int sub = 0; sub < 2; sub++) {
            const int b0 = bc * (2 * NB) + sub * NB;
            float* csub = cs + sub * (NB * JT);

            // ---- stage u (vsp rows 0..19) ----
            for (int idx = tid; idx < RNK * 64; idx += 512) {
                int r = idx >> 6, bb = idx & 63;
                if (bb < NB) {
                    int b = b0 + bb;
                    float v = (b < BATCH) ? g_u[(t * RNK + r) * BATCH + b] : 0.f;
                    vsp[r * NB + bb] = pack2(v, v);
                }
            }
            if (sub == 1) {
                // hu data already available (sub0 waited); stage rows 20..39 now
                for (int idx = tid; idx < RNK * 64; idx += 512) {
                    int r = idx >> 6, bb = idx & 63;
                    if (bb < NB) {
                        int b = b0 + bb;
                        float v = 0.f;
                        if (t > 0 && b < BATCH) {
                            const float* p = rd + r * (NJT * BATCH) + b;
                            v = (__ldcg(p) + __ldcg(p + BATCH))
                              + (__ldcg(p + 2 * BATCH) + __ldcg(p + 3 * BATCH));
                        }
                        vsp[(RNK + r) * NB + bb] = pack2(v, v);
                    }
                }
            }
            __syncthreads();

            // ---- GEMM (sub0: split around grid barrier; sub1: full) ----
            ull acc[4][7];
#pragma unroll
            for (int g = 0; g < 4; g++) {
                ull bg = *reinterpret_cast<const ull*>(bs + g * 128 + jjl0);
#pragma unroll
                for (int n = 0; n < 7; n++) acc[g][n] = bg;
            }

            if (sub == 0) {
                gemm_part<0, RNK>(acc, wT, vsp, jjl0, bb0);   // u half, hides barrier
                if (t > 0 && tid == 0) {
                    unsigned target = (unsigned)NBLK * (unsigned)t;
                    while (bar_peek(&g_bar) < target) __nanosleep(64);
                }
                __syncthreads();
                // stage hu (vsp rows 20..39)
                for (int idx = tid; idx < RNK * 64; idx += 512) {
                    int r = idx >> 6, bb = idx & 63;
                    if (bb < NB) {
                        int b = b0 + bb;
                        float v = 0.f;
                        if (t > 0 && b < BATCH) {
                            const float* p = rd + r * (NJT * BATCH) + b;
                            v = (__ldcg(p) + __ldcg(p + BATCH))
                              + (__ldcg(p + 2 * BATCH) + __ldcg(p + 3 * BATCH));
                        }
                        vsp[(RNK + r) * NB + bb] = pack2(v, v);
                    }
                }
                __syncthreads();
                gemm_part<RNK, 2 * RNK>(acc, wT, vsp, jjl0, bb0);
            } else {
                gemm_part<0, 2 * RNK>(acc, wT, vsp, jjl0, bb0);
            }

            // ---- epilogue: cell update; c in smem ----
#pragma unroll
            for (int n = 0; n < 7; n++) {
                int bb = bb0 + n;
                int b = b0 + bb;
                float2 i2 = unpack2(acc[0][n]);
                float2 f2 = unpack2(acc[1][n]);
                float2 g2 = unpack2(acc[2][n]);
                float2 o2 = unpack2(acc[3][n]);
                float2 cold = (t > 0)
                    ? *reinterpret_cast<const float2*>(csub + bb * JT + jjl0)
                    : make_float2(0.f, 0.f);
                float2 cc, hh;
                cc.x = fmaf(siga(f2.x), cold.x, siga(i2.x) * tanha(g2.x));
                cc.y = fmaf(siga(f2.y), cold.y, siga(i2.y) * tanha(g2.y));
                hh.x = siga(o2.x) * tanha(cc.x);
                hh.y = siga(o2.y) * tanha(cc.y);
                *reinterpret_cast<float2*>(csub + bb * JT + jjl0) = cc;
                *reinterpret_cast<float2*>(ht + bb * HSTRD + jjl0) = hh;
                if (b < BATCH) {
                    *reinterpret_cast<float2*>(out + ((long)b * TSEQ + t) * HSZ + j0 + jjl0) = hh;
                    if (lastT && hdst) {
                        *reinterpret_cast<float2*>(hdst + (long)b * HSZ + j0 + jjl0) = hh;
                        *reinterpret_cast<float2*>(cdst + (long)b * HSZ + j0 + jjl0) = cc;
                    }
                }
            }
            __syncthreads();

            // ---- hu partials into vsp region: (js 0-3, rh 0-1, bb 0-55) ----
            {
                ull* part = vsp;                 // vsp dead after GEMM
                const int js = tid >> 7, rh = (tid >> 6) & 1, bb = tid & 63;
                if (bb < NB) {
                    ull a5[5];
#pragma unroll
                    for (int q = 0; q < 5; q++) a5[q] = 0ull;
                    const int jbeg = js * 32;
#pragma unroll 4
                    for (int jj = 0; jj < 32; jj++) {
                        int j = jbeg + jj;
                        float hv = ht[bb * HSTRD + j];
                        ull hs2 = pack2(hv, hv);
                        const float* wrow = wa + j * RNK + rh * 10;
#pragma unroll
                        for (int q = 0; q < 5; q++)
                            ffma2(a5[q], hs2, *reinterpret_cast<const ull*>(wrow + 2 * q));
                    }
#pragma unroll
                    for (int q = 0; q < 5; q++)
                        part[((rh * 5 + q) * 4 + js) * NB + bb] = a5[q];
                }
            }
            __syncthreads();

            // ---- reduce 4 jslices -> g_hu[r][jt][B]  (640 items, 512 threads: loop!) ----
            for (int o = tid; o < 640; o += 512) {
                const ull* part = vsp;
                int bb = o & 63, rp = o >> 6;
                if (bb < NB) {
                    int b = b0 + bb;
                    ull s = add2(add2(part[(rp * 4 + 0) * NB + bb], part[(rp * 4 + 1) * NB + bb]),
                                 add2(part[(rp * 4 + 2) * NB + bb], part[(rp * 4 + 3) * NB + bb]));
                    float2 f = unpack2(s);
                    if (b < BATCH) {
                        wr[((2 * rp + 0) * NJT + jt) * BATCH + b] = f.x;
                        wr[((2 * rp + 1) * NJT + jt) * BATCH + b] = f.y;
                    }
                }
            }
            __syncthreads();
        }

        if (t < TSEQ - 1 && tid == 0) bar_arrive(&g_bar);
    }
}

// ---------------------------------------------------------------------------
extern "C" void kernel_launch(void* const* d_in, const int* in_sizes, int n_in,
                              void* d_out, int out_size) {
    const float* x     = (const float*)d_in[0];
    const float* wih_a = (const float*)d_in[1];
    const float* wih_b = (const float*)d_in[2];
    const float* b_ih  = (const float*)d_in[3];
    const float* whh_a = (const float*)d_in[4];
    const float* whh_b = (const float*)d_in[5];
    const float* b_hh  = (const float*)d_in[6];
    float* out = (float*)d_out;

    const long BTH = (long)BATCH * TSEQ * HSZ;
    float* hdst = nullptr;
    float* cdst = nullptr;
    if ((long)out_size >= BTH + 2L * BATCH * HSZ) {
        hdst = out + BTH;
        cdst = hdst + (long)BATCH * HSZ;
    }

    cudaFuncSetAttribute(kStep, cudaFuncAttributeMaxDynamicSharedMemorySize,
                         SMEM_FLOATS * 4);

    kPre<<<(BATCH * TSEQ) / 256, 256>>>(x, wih_a);
    kStep<<<NBLK, 512, SMEM_FLOATS * 4>>>(wih_b, b_ih, whh_a, whh_b, b_hh,
                                          out, hdst, cdst);
}